// round 11
// baseline (speedup 1.0000x reference)
#include <cuda_runtime.h>
#include <cuda_fp16.h>
#include <cstdint>
#include <math.h>

// Problem constants (fixed by the dataset)
#define BATCH 4
#define SEQL  2048
#define NH    8
#define HDIM  64
#define BM    64        // query rows per CTA (4 warps x 16)
#define BN    64        // key rows per iteration
#define RS    (NH * HDIM)   // 512 floats between seq positions
#define HSTR  72        // fp16 tile row stride (halfs), K and V^T alike

// fp16 scratch: K as [b,h,s,e], V transposed as [b,h,d,s]
__device__ __half g_Kh[(size_t)BATCH * NH * SEQL * HDIM];
__device__ __half g_Vt[(size_t)BATCH * NH * HDIM * SEQL];

// stage = K tile (64 rows x 72) + V^T tile (72 rows x 72; rows 64..71 = ones)
#define K_HALFS     (BN * HSTR)                  // 4608
#define STAGE_HALFS (K_HALFS + 72 * HSTR)        // 9792
#define SMEM_BYTES  (2 * STAGE_HALFS * 2)        // 39168 (double buffered)

__device__ __forceinline__ float ex2(float x) {
    float y;
    asm("ex2.approx.ftz.f32 %0, %1;" : "=f"(y) : "f"(x));
    return y;
}
__device__ __forceinline__ uint32_t ex2h2(uint32_t x) {   // two fp16 exp2 in one MUFU op
    uint32_t y;
    asm("ex2.approx.f16x2 %0, %1;" : "=r"(y) : "r"(x));
    return y;
}
__device__ __forceinline__ uint32_t packh2(float lo, float hi) {
    half2 h = __floats2half2_rn(lo, hi);
    return *reinterpret_cast<uint32_t*>(&h);
}

__device__ __forceinline__ void mma16(float c[4],
                                      uint32_t a0, uint32_t a1, uint32_t a2, uint32_t a3,
                                      uint32_t b0, uint32_t b1) {
    asm volatile(
        "mma.sync.aligned.m16n8k16.row.col.f32.f16.f16.f32 "
        "{%0,%1,%2,%3}, {%4,%5,%6,%7}, {%8,%9}, {%0,%1,%2,%3};"
        : "+f"(c[0]), "+f"(c[1]), "+f"(c[2]), "+f"(c[3])
        : "r"(a0), "r"(a1), "r"(a2), "r"(a3), "r"(b0), "r"(b1));
}

__device__ __forceinline__ void ldsm4(uint32_t r[4], uint32_t saddr) {
    asm volatile("ldmatrix.sync.aligned.m8n8.x4.shared.b16 {%0,%1,%2,%3}, [%4];"
        : "=r"(r[0]), "=r"(r[1]), "=r"(r[2]), "=r"(r[3]) : "r"(saddr));
}

__device__ __forceinline__ void cpasync16(uint32_t saddr, const void* g) {
    asm volatile("cp.async.cg.shared.global [%0], [%1], 16;\n"
                 :: "r"(saddr), "l"(g));
}

// ---------------- fused prepass: K relayout + V transpose, both fp32->fp16 ----------------
__global__ void conv_kernel(const float* __restrict__ K, const float* __restrict__ V)
{
    __shared__ float st[64 * 65];
    const int bh = blockIdx.y;
    const int b  = bh >> 3;
    const int h  = bh & 7;
    const int s0 = blockIdx.x * 64;
    const int tid = threadIdx.x;   // 256

    __half* outK = g_Kh + (size_t)bh * SEQL * HDIM;
    #pragma unroll
    for (int i = 0; i < 4; i++) {
        int idx = i * 256 + tid;
        int r   = idx >> 4;
        int c4  = (idx & 15) << 2;
        float4 v = *reinterpret_cast<const float4*>(
            K + ((size_t)((size_t)b * SEQL + s0 + r) * NH + h) * HDIM + c4);
        uint2 w;
        w.x = packh2(v.x, v.y);
        w.y = packh2(v.z, v.w);
        *reinterpret_cast<uint2*>(outK + (size_t)(s0 + r) * HDIM + c4) = w;
    }

    #pragma unroll
    for (int i = 0; i < 4; i++) {
        int idx = i * 256 + tid;
        int r   = idx >> 4;
        int c4  = (idx & 15) << 2;
        float4 v = *reinterpret_cast<const float4*>(
            V + ((size_t)((size_t)b * SEQL + s0 + r) * NH + h) * HDIM + c4);
        float* dst = &st[r * 65 + c4];
        dst[0] = v.x; dst[1] = v.y; dst[2] = v.z; dst[3] = v.w;
    }
    __syncthreads();

    __half* outV = g_Vt + (size_t)bh * HDIM * SEQL;
    #pragma unroll
    for (int i = 0; i < 8; i++) {
        int idx = i * 256 + tid;
        int d   = idx >> 5;
        int s2  = idx & 31;
        __half2 w = __floats2half2_rn(st[(2 * s2) * 65 + d],
                                      st[(2 * s2 + 1) * 65 + d]);
        *reinterpret_cast<__half2*>(outV + (size_t)d * SEQL + s0 + 2 * s2) = w;
    }
}

// ---------------- main attention kernel ----------------
__global__ __launch_bounds__(128, 3)
void fa_fp16_kernel(const float* __restrict__ Q,
                    float* __restrict__ O)
{
    extern __shared__ __half sh[];
    __half* const stage0 = sh;
    __half* const stage1 = sh + STAGE_HALFS;
    float*  const sQf    = reinterpret_cast<float*>(stage1);   // prologue overlay (16KB < 18.4KB safe region)

    const int tid  = threadIdx.x;
    const int warp = tid >> 5;
    const int lane = tid & 31;
    const int qd   = lane & 3;
    const int g    = lane >> 2;

    const int bh = blockIdx.y;
    const int b  = bh >> 3;
    const int h  = bh & 7;
    // heavy tiles first
    const int qblk = (SEQL / BM - 1) - blockIdx.x;
    const int m0   = qblk * BM;
    const int nblk = qblk + 1;

    const float qscale = 0.125f * 1.4426950408889634f;  // 1/sqrt(64) * log2(e)

    const float*  Qb  = Q + ((size_t)((size_t)b * SEQL + m0) * NH + h) * HDIM;
    const __half* Khb = g_Kh + (size_t)bh * SEQL * HDIM;
    const __half* Vtb = g_Vt + (size_t)bh * HDIM * SEQL;

    // per-lane ldmatrix row offset (halfs): row lane&7, matrix lane>>3
    const int lrow = (lane & 7) * HSTR + 8 * (lane >> 3);

    // ---- prologue: async-load fp16 tile 0; init ones-rows (d=64..71) in both stages
    {
        __half* dK = stage0;
        __half* dV = stage0 + K_HALFS;
        #pragma unroll
        for (int i = 0; i < 4; i++) {
            int idx = i * 128 + tid;       // 64 rows x 8 chunks of 16B
            int r   = idx >> 3;
            int gr  = idx & 7;
            cpasync16((uint32_t)__cvta_generic_to_shared(dK + r * HSTR + 8 * gr),
                      Khb + (size_t)r * HDIM + 8 * gr);
            cpasync16((uint32_t)__cvta_generic_to_shared(dV + r * HSTR + 8 * gr),
                      Vtb + (size_t)r * SEQL + 8 * gr);
        }
        asm volatile("cp.async.commit_group;\n");

        // ones rows: V^T rows 64..71 (halfs [K_HALFS+64*HSTR, K_HALFS+72*HSTR))
        const uint32_t one2 = 0x3C003C00u;   // half2(1.0, 1.0)
        uint32_t* z0 = reinterpret_cast<uint32_t*>(stage0) + (K_HALFS + 64 * HSTR) / 2;
        uint32_t* z1 = reinterpret_cast<uint32_t*>(stage1) + (K_HALFS + 64 * HSTR) / 2;
        for (int i = tid; i < 8 * HSTR / 2; i += 128) { z0[i] = one2; z1[i] = one2; }
    }

    // ---- stage Q (fp32) into overlay, build fp16 A-frags with scale folded in
    #pragma unroll
    for (int i = 0; i < 8; i++) {
        int idx = i * 128 + tid;
        int r   = idx >> 4;
        int c4  = (idx & 15) << 2;
        float4 v = *reinterpret_cast<const float4*>(Qb + (size_t)r * RS + c4);
        float* dst = &sQf[r * 64 + c4];
        dst[0] = v.x; dst[1] = v.y; dst[2] = v.z; dst[3] = v.w;
    }
    __syncthreads();

    const int r0    = warp * 16 + g;
    const int grow0 = m0 + r0;
    const int grow1 = grow0 + 8;

    uint32_t qa[4][4];
    #pragma unroll
    for (int kk = 0; kk < 4; kk++) {
        const float* qr0 = &sQf[r0 * 64 + 16 * kk + 2 * qd];
        const float* qr1 = &sQf[(r0 + 8) * 64 + 16 * kk + 2 * qd];
        qa[kk][0] = packh2(qr0[0] * qscale, qr0[1] * qscale);
        qa[kk][1] = packh2(qr1[0] * qscale, qr1[1] * qscale);
        qa[kk][2] = packh2(qr0[8] * qscale, qr0[9] * qscale);
        qa[kk][3] = packh2(qr1[8] * qscale, qr1[9] * qscale);
    }

    // o[0..7] = output accumulators; o[8] = l (ones-column of V^T)
    float o[9][4];
    #pragma unroll
    for (int n = 0; n < 9; n++)
        #pragma unroll
        for (int i = 0; i < 4; i++) o[n][i] = 0.f;

    float mrow0 = -INFINITY, mrow1 = -INFINITY;

    for (int j = 0; j < nblk; j++) {
        __half* const st = (j & 1) ? stage1 : stage0;
        const uint32_t kbase = (uint32_t)__cvta_generic_to_shared(st) + lrow * 2;
        const uint32_t vbase = kbase + K_HALFS * 2;

        asm volatile("cp.async.wait_group 0;\n");
        __syncthreads();   // tile j visible; stage[(j+1)&1] fully consumed

        // ---- prefetch tile j+1
        if (j + 1 < nblk) {
            __half* const nst = (j & 1) ? stage0 : stage1;
            __half* dK = nst;
            __half* dV = nst + K_HALFS;
            #pragma unroll
            for (int i = 0; i < 4; i++) {
                int idx = i * 128 + tid;
                int r   = idx >> 3;
                int gr  = idx & 7;
                cpasync16((uint32_t)__cvta_generic_to_shared(dK + r * HSTR + 8 * gr),
                          Khb + (size_t)(j + 1) * BN * HDIM + (size_t)r * HDIM + 8 * gr);
                cpasync16((uint32_t)__cvta_generic_to_shared(dV + r * HSTR + 8 * gr),
                          Vtb + (size_t)r * SEQL + (j + 1) * BN + 8 * gr);
            }
            asm volatile("cp.async.commit_group;\n");
        }

        // ---- S = Q K^T : B-frags via ldmatrix.x4
        float c[8][4];
        #pragma unroll
        for (int n = 0; n < 8; n++)
            #pragma unroll
            for (int i = 0; i < 4; i++) c[n][i] = 0.f;

        #pragma unroll
        for (int n = 0; n < 8; n++) {
            uint32_t kb[8];
            uint32_t a0 = kbase + (8 * n * HSTR) * 2;
            ldsm4(kb,     a0);
            ldsm4(kb + 4, a0 + 64);
            mma16(c[n], qa[0][0], qa[0][1], qa[0][2], qa[0][3], kb[0], kb[1]);
            mma16(c[n], qa[1][0], qa[1][1], qa[1][2], qa[1][3], kb[2], kb[3]);
            mma16(c[n], qa[2][0], qa[2][1], qa[2][2], qa[2][3], kb[4], kb[5]);
            mma16(c[n], qa[3][0], qa[3][1], qa[3][2], qa[3][3], kb[6], kb[7]);
        }

        // ---- causal mask (diagonal tile only)
        if (j == qblk) {
            #pragma unroll
            for (int n = 0; n < 8; n++) {
                int colb = j * BN + n * 8 + 2 * qd;
                if (colb     > grow0) c[n][0] = -INFINITY;
                if (colb + 1 > grow0) c[n][1] = -INFINITY;
                if (colb     > grow1) c[n][2] = -INFINITY;
                if (colb + 1 > grow1) c[n][3] = -INFINITY;
            }
        }

        // ---- online softmax (log2 domain)
        float tm0 = -INFINITY, tm1 = -INFINITY;
        #pragma unroll
        for (int n = 0; n < 8; n++) {
            tm0 = fmaxf(tm0, fmaxf(c[n][0], c[n][1]));
            tm1 = fmaxf(tm1, fmaxf(c[n][2], c[n][3]));
        }
        tm0 = fmaxf(tm0, __shfl_xor_sync(0xffffffffu, tm0, 1));
        tm0 = fmaxf(tm0, __shfl_xor_sync(0xffffffffu, tm0, 2));
        tm1 = fmaxf(tm1, __shfl_xor_sync(0xffffffffu, tm1, 1));
        tm1 = fmaxf(tm1, __shfl_xor_sync(0xffffffffu, tm1, 2));

        float mn0 = fmaxf(mrow0, tm0);
        float mn1 = fmaxf(mrow1, tm1);
        float a0 = ex2(mrow0 - mn0);
        float a1 = ex2(mrow1 - mn1);
        mrow0 = mn0; mrow1 = mn1;

        // rescale all accumulators incl. l (o[8])
        #pragma unroll
        for (int n = 0; n < 9; n++) {
            o[n][0] *= a0; o[n][1] *= a0;
            o[n][2] *= a1; o[n][3] *= a1;
        }

        // P = exp2(c - mn), computed pairwise in fp16 (one MUFU per pair),
        // result IS the PV A-fragment — no separate pack, no l accumulation.
        uint32_t hp[8][2];
        #pragma unroll
        for (int n = 0; n < 8; n++) {
            hp[n][0] = ex2h2(packh2(c[n][0] - mn0, c[n][1] - mn0));
            hp[n][1] = ex2h2(packh2(c[n][2] - mn1, c[n][3] - mn1));
        }

        // ---- O += P V ; n=8 is the ones-column -> accumulates l in o[8]
        #pragma unroll
        for (int n = 0; n < 9; n++) {
            uint32_t vb[8];
            uint32_t a0v = vbase + (8 * n * HSTR) * 2;
            ldsm4(vb,     a0v);
            ldsm4(vb + 4, a0v + 64);
            mma16(o[n], hp[0][0], hp[0][1], hp[1][0], hp[1][1], vb[0], vb[1]);
            mma16(o[n], hp[2][0], hp[2][1], hp[3][0], hp[3][1], vb[2], vb[3]);
            mma16(o[n], hp[4][0], hp[4][1], hp[5][0], hp[5][1], vb[4], vb[5]);
            mma16(o[n], hp[6][0], hp[6][1], hp[7][0], hp[7][1], vb[6], vb[7]);
        }
    }

    // ---- finalize: l sits in o[8] (all lanes identical per row group)
    const float inv0 = 1.f / o[8][0];
    const float inv1 = 1.f / o[8][2];

    float* Ob0 = O + ((size_t)((size_t)b * SEQL + grow0) * NH + h) * HDIM;
    float* Ob1 = O + ((size_t)((size_t)b * SEQL + grow1) * NH + h) * HDIM;
    #pragma unroll
    for (int n = 0; n < 8; n++) {
        int col = n * 8 + 2 * qd;
        *reinterpret_cast<float2*>(Ob0 + col) =
            make_float2(o[n][0] * inv0, o[n][1] * inv0);
        *reinterpret_cast<float2*>(Ob1 + col) =
            make_float2(o[n][2] * inv1, o[n][3] * inv1);
    }
}

extern "C" void kernel_launch(void* const* d_in, const int* in_sizes, int n_in,
                              void* d_out, int out_size)
{
    const float* Q = (const float*)d_in[0];
    const float* K = (const float*)d_in[1];
    const float* V = (const float*)d_in[2];
    float* O = (float*)d_out;

    // fused prepass: K relayout + V transpose to fp16 scratch
    conv_kernel<<<dim3(SEQL / 64, BATCH * NH), 256>>>(K, V);

    cudaFuncSetAttribute(fa_fp16_kernel,
                         cudaFuncAttributeMaxDynamicSharedMemorySize, SMEM_BYTES);
    dim3 grid(SEQL / BM, BATCH * NH);   // (32, 32)
    fa_fp16_kernel<<<grid, 128, SMEM_BYTES>>>(Q, O);
}

// round 12
// speedup vs baseline: 1.0123x; 1.0123x over previous
#include <cuda_runtime.h>
#include <cuda_fp16.h>
#include <cstdint>
#include <math.h>

// Problem constants (fixed by the dataset)
#define BATCH 4
#define SEQL  2048
#define NH    8
#define HDIM  64
#define BM    64        // query rows per CTA (4 warps x 16)
#define BN    64        // key rows per iteration
#define RS    (NH * HDIM)   // 512 floats between seq positions
#define HSTR  72        // fp16 tile row stride (halfs), K and V^T alike

// fp16 scratch: K as [b,h,s,e], V transposed as [b,h,d,s]
__device__ __half g_Kh[(size_t)BATCH * NH * SEQL * HDIM];
__device__ __half g_Vt[(size_t)BATCH * NH * HDIM * SEQL];

// stage = K tile (64 rows x 72) + V^T tile (72 rows x 72; rows 64..71 = ones)
#define K_HALFS     (BN * HSTR)                  // 4608
#define STAGE_HALFS (K_HALFS + 72 * HSTR)        // 9792
#define SMEM_BYTES  (2 * STAGE_HALFS * 2)        // 39168 (double buffered)

__device__ __forceinline__ float ex2(float x) {
    float y;
    asm("ex2.approx.ftz.f32 %0, %1;" : "=f"(y) : "f"(x));
    return y;
}
__device__ __forceinline__ uint32_t ex2h2(uint32_t x) {   // two fp16 exp2 in one MUFU op
    uint32_t y;
    asm("ex2.approx.f16x2 %0, %1;" : "=r"(y) : "r"(x));
    return y;
}
__device__ __forceinline__ uint32_t packh2(float lo, float hi) {
    half2 h = __floats2half2_rn(lo, hi);
    return *reinterpret_cast<uint32_t*>(&h);
}

__device__ __forceinline__ void mma16(float c[4],
                                      uint32_t a0, uint32_t a1, uint32_t a2, uint32_t a3,
                                      uint32_t b0, uint32_t b1) {
    asm volatile(
        "mma.sync.aligned.m16n8k16.row.col.f32.f16.f16.f32 "
        "{%0,%1,%2,%3}, {%4,%5,%6,%7}, {%8,%9}, {%0,%1,%2,%3};"
        : "+f"(c[0]), "+f"(c[1]), "+f"(c[2]), "+f"(c[3])
        : "r"(a0), "r"(a1), "r"(a2), "r"(a3), "r"(b0), "r"(b1));
}

__device__ __forceinline__ void ldsm4(uint32_t r[4], uint32_t saddr) {
    asm volatile("ldmatrix.sync.aligned.m8n8.x4.shared.b16 {%0,%1,%2,%3}, [%4];"
        : "=r"(r[0]), "=r"(r[1]), "=r"(r[2]), "=r"(r[3]) : "r"(saddr));
}

__device__ __forceinline__ void cpasync16(uint32_t saddr, const void* g) {
    asm volatile("cp.async.cg.shared.global [%0], [%1], 16;\n"
                 :: "r"(saddr), "l"(g));
}

// ---------------- fused prepass: K relayout + V transpose, both fp32->fp16 ----------------
__global__ void conv_kernel(const float* __restrict__ K, const float* __restrict__ V)
{
    __shared__ float st[64 * 65];
    const int bh = blockIdx.y;
    const int b  = bh >> 3;
    const int h  = bh & 7;
    const int s0 = blockIdx.x * 64;
    const int tid = threadIdx.x;   // 256

    __half* outK = g_Kh + (size_t)bh * SEQL * HDIM;
    #pragma unroll
    for (int i = 0; i < 4; i++) {
        int idx = i * 256 + tid;
        int r   = idx >> 4;
        int c4  = (idx & 15) << 2;
        float4 v = *reinterpret_cast<const float4*>(
            K + ((size_t)((size_t)b * SEQL + s0 + r) * NH + h) * HDIM + c4);
        uint2 w;
        w.x = packh2(v.x, v.y);
        w.y = packh2(v.z, v.w);
        *reinterpret_cast<uint2*>(outK + (size_t)(s0 + r) * HDIM + c4) = w;
    }

    #pragma unroll
    for (int i = 0; i < 4; i++) {
        int idx = i * 256 + tid;
        int r   = idx >> 4;
        int c4  = (idx & 15) << 2;
        float4 v = *reinterpret_cast<const float4*>(
            V + ((size_t)((size_t)b * SEQL + s0 + r) * NH + h) * HDIM + c4);
        float* dst = &st[r * 65 + c4];
        dst[0] = v.x; dst[1] = v.y; dst[2] = v.z; dst[3] = v.w;
    }
    __syncthreads();

    __half* outV = g_Vt + (size_t)bh * HDIM * SEQL;
    #pragma unroll
    for (int i = 0; i < 8; i++) {
        int idx = i * 256 + tid;
        int d   = idx >> 5;
        int s2  = idx & 31;
        __half2 w = __floats2half2_rn(st[(2 * s2) * 65 + d],
                                      st[(2 * s2 + 1) * 65 + d]);
        *reinterpret_cast<__half2*>(outV + (size_t)d * SEQL + s0 + 2 * s2) = w;
    }
}

// ---------------- main attention kernel ----------------
__global__ __launch_bounds__(128, 3)
void fa_fp16_kernel(const float* __restrict__ Q,
                    float* __restrict__ O)
{
    extern __shared__ __half sh[];
    __half* const stage0 = sh;
    __half* const stage1 = sh + STAGE_HALFS;
    float*  const sQf    = reinterpret_cast<float*>(stage1);   // prologue overlay

    const int tid  = threadIdx.x;
    const int warp = tid >> 5;
    const int lane = tid & 31;
    const int qd   = lane & 3;
    const int g    = lane >> 2;

    const int bh = blockIdx.y;
    const int b  = bh >> 3;
    const int h  = bh & 7;
    // heavy tiles first
    const int qblk = (SEQL / BM - 1) - blockIdx.x;
    const int m0   = qblk * BM;
    const int nblk = qblk + 1;

    const float qscale = 0.125f * 1.4426950408889634f;  // 1/sqrt(64) * log2(e)

    const float*  Qb  = Q + ((size_t)((size_t)b * SEQL + m0) * NH + h) * HDIM;
    const __half* Khb = g_Kh + (size_t)bh * SEQL * HDIM;
    const __half* Vtb = g_Vt + (size_t)bh * HDIM * SEQL;

    // per-lane ldmatrix row offset (halfs): row lane&7, matrix lane>>3
    const int lrow = (lane & 7) * HSTR + 8 * (lane >> 3);

    // ---- prologue: async-load fp16 tile 0; init ones-rows (d=64..71) in both stages
    {
        __half* dK = stage0;
        __half* dV = stage0 + K_HALFS;
        #pragma unroll
        for (int i = 0; i < 4; i++) {
            int idx = i * 128 + tid;       // 64 rows x 8 chunks of 16B
            int r   = idx >> 3;
            int gr  = idx & 7;
            cpasync16((uint32_t)__cvta_generic_to_shared(dK + r * HSTR + 8 * gr),
                      Khb + (size_t)r * HDIM + 8 * gr);
            cpasync16((uint32_t)__cvta_generic_to_shared(dV + r * HSTR + 8 * gr),
                      Vtb + (size_t)r * SEQL + 8 * gr);
        }
        asm volatile("cp.async.commit_group;\n");

        const uint32_t one2 = 0x3C003C00u;   // half2(1.0, 1.0)
        uint32_t* z0 = reinterpret_cast<uint32_t*>(stage0) + (K_HALFS + 64 * HSTR) / 2;
        uint32_t* z1 = reinterpret_cast<uint32_t*>(stage1) + (K_HALFS + 64 * HSTR) / 2;
        for (int i = tid; i < 8 * HSTR / 2; i += 128) { z0[i] = one2; z1[i] = one2; }
    }

    // ---- stage Q (fp32) into overlay, build fp16 A-frags with scale folded in
    #pragma unroll
    for (int i = 0; i < 8; i++) {
        int idx = i * 128 + tid;
        int r   = idx >> 4;
        int c4  = (idx & 15) << 2;
        float4 v = *reinterpret_cast<const float4*>(Qb + (size_t)r * RS + c4);
        float* dst = &sQf[r * 64 + c4];
        dst[0] = v.x; dst[1] = v.y; dst[2] = v.z; dst[3] = v.w;
    }
    __syncthreads();

    const int r0    = warp * 16 + g;
    const int grow0 = m0 + r0;
    const int grow1 = grow0 + 8;

    uint32_t qa[4][4];
    #pragma unroll
    for (int kk = 0; kk < 4; kk++) {
        const float* qr0 = &sQf[r0 * 64 + 16 * kk + 2 * qd];
        const float* qr1 = &sQf[(r0 + 8) * 64 + 16 * kk + 2 * qd];
        qa[kk][0] = packh2(qr0[0] * qscale, qr0[1] * qscale);
        qa[kk][1] = packh2(qr1[0] * qscale, qr1[1] * qscale);
        qa[kk][2] = packh2(qr0[8] * qscale, qr0[9] * qscale);
        qa[kk][3] = packh2(qr1[8] * qscale, qr1[9] * qscale);
    }

    // o[0..7] = output accumulators; o[8] = l (ones-column of V^T)
    float o[9][4];
    #pragma unroll
    for (int n = 0; n < 9; n++)
        #pragma unroll
        for (int i = 0; i < 4; i++) o[n][i] = 0.f;

    // lagged reference max per row group (quad-uniform by construction)
    float mref0 = -INFINITY, mref1 = -INFINITY;

    for (int j = 0; j < nblk; j++) {
        __half* const st = (j & 1) ? stage1 : stage0;
        const uint32_t kbase = (uint32_t)__cvta_generic_to_shared(st) + lrow * 2;
        const uint32_t vbase = kbase + K_HALFS * 2;

        asm volatile("cp.async.wait_group 0;\n");
        __syncthreads();   // tile j visible; stage[(j+1)&1] fully consumed

        // ---- prefetch tile j+1
        if (j + 1 < nblk) {
            __half* const nst = (j & 1) ? stage0 : stage1;
            __half* dK = nst;
            __half* dV = nst + K_HALFS;
            #pragma unroll
            for (int i = 0; i < 4; i++) {
                int idx = i * 128 + tid;
                int r   = idx >> 3;
                int gr  = idx & 7;
                cpasync16((uint32_t)__cvta_generic_to_shared(dK + r * HSTR + 8 * gr),
                          Khb + (size_t)(j + 1) * BN * HDIM + (size_t)r * HDIM + 8 * gr);
                cpasync16((uint32_t)__cvta_generic_to_shared(dV + r * HSTR + 8 * gr),
                          Vtb + (size_t)r * SEQL + (j + 1) * BN + 8 * gr);
            }
            asm volatile("cp.async.commit_group;\n");
        }

        // ---- S = Q K^T : B-frags via ldmatrix.x4
        float c[8][4];
        #pragma unroll
        for (int n = 0; n < 8; n++)
            #pragma unroll
            for (int i = 0; i < 4; i++) c[n][i] = 0.f;

        #pragma unroll
        for (int n = 0; n < 8; n++) {
            uint32_t kb[8];
            uint32_t a0 = kbase + (8 * n * HSTR) * 2;
            ldsm4(kb,     a0);
            ldsm4(kb + 4, a0 + 64);
            mma16(c[n], qa[0][0], qa[0][1], qa[0][2], qa[0][3], kb[0], kb[1]);
            mma16(c[n], qa[1][0], qa[1][1], qa[1][2], qa[1][3], kb[2], kb[3]);
            mma16(c[n], qa[2][0], qa[2][1], qa[2][2], qa[2][3], kb[4], kb[5]);
            mma16(c[n], qa[3][0], qa[3][1], qa[3][2], qa[3][3], kb[6], kb[7]);
        }

        // ---- causal mask (diagonal tile only)
        if (j == qblk) {
            #pragma unroll
            for (int n = 0; n < 8; n++) {
                int colb = j * BN + n * 8 + 2 * qd;
                if (colb     > grow0) c[n][0] = -INFINITY;
                if (colb + 1 > grow0) c[n][1] = -INFINITY;
                if (colb     > grow1) c[n][2] = -INFINITY;
                if (colb + 1 > grow1) c[n][3] = -INFINITY;
            }
        }

        // ---- deferred-max softmax: no cross-lane reduce on the fast path.
        // Per-thread tile max (parallel fmax tree).
        float t0 = fmaxf(fmaxf(c[0][0], c[0][1]), fmaxf(c[1][0], c[1][1]));
        float t1 = fmaxf(fmaxf(c[0][2], c[0][3]), fmaxf(c[1][2], c[1][3]));
        #pragma unroll
        for (int n = 2; n < 8; n += 2) {
            t0 = fmaxf(t0, fmaxf(fmaxf(c[n][0], c[n][1]), fmaxf(c[n + 1][0], c[n + 1][1])));
            t1 = fmaxf(t1, fmaxf(fmaxf(c[n][2], c[n][3]), fmaxf(c[n + 1][2], c[n + 1][3])));
        }
        // rescale only if exp2(c - mref) could overflow fp16 headroom (p <= 2^8)
        if (__any_sync(0xffffffffu, fmaxf(t0 - mref0, t1 - mref1) > 8.f)) {
            t0 = fmaxf(t0, __shfl_xor_sync(0xffffffffu, t0, 1));
            t0 = fmaxf(t0, __shfl_xor_sync(0xffffffffu, t0, 2));
            t1 = fmaxf(t1, __shfl_xor_sync(0xffffffffu, t1, 1));
            t1 = fmaxf(t1, __shfl_xor_sync(0xffffffffu, t1, 2));
            float n0 = fmaxf(mref0, t0);
            float n1 = fmaxf(mref1, t1);
            float a0 = ex2(mref0 - n0);    // ex2(-inf) = 0 on first trigger; o==0 anyway
            float a1 = ex2(mref1 - n1);
            mref0 = n0; mref1 = n1;
            #pragma unroll
            for (int n = 0; n < 9; n++) {
                o[n][0] *= a0; o[n][1] *= a0;
                o[n][2] *= a1; o[n][3] *= a1;
            }
        }

        // P = exp2(c - mref) pairwise in fp16; result IS the PV A-fragment.
        uint32_t hp[8][2];
        #pragma unroll
        for (int n = 0; n < 8; n++) {
            hp[n][0] = ex2h2(packh2(c[n][0] - mref0, c[n][1] - mref0));
            hp[n][1] = ex2h2(packh2(c[n][2] - mref1, c[n][3] - mref1));
        }

        // ---- O += P V ; n=8 is the ones-column -> accumulates l in o[8]
        #pragma unroll
        for (int n = 0; n < 9; n++) {
            uint32_t vb[8];
            uint32_t a0v = vbase + (8 * n * HSTR) * 2;
            ldsm4(vb,     a0v);
            ldsm4(vb + 4, a0v + 64);
            mma16(o[n], hp[0][0], hp[0][1], hp[1][0], hp[1][1], vb[0], vb[1]);
            mma16(o[n], hp[2][0], hp[2][1], hp[3][0], hp[3][1], vb[2], vb[3]);
            mma16(o[n], hp[4][0], hp[4][1], hp[5][0], hp[5][1], vb[4], vb[5]);
            mma16(o[n], hp[6][0], hp[6][1], hp[7][0], hp[7][1], vb[6], vb[7]);
        }
    }

    // ---- finalize: l sits in o[8]; frame factor 2^-mref cancels in O/l
    const float inv0 = 1.f / o[8][0];
    const float inv1 = 1.f / o[8][2];

    float* Ob0 = O + ((size_t)((size_t)b * SEQL + grow0) * NH + h) * HDIM;
    float* Ob1 = O + ((size_t)((size_t)b * SEQL + grow1) * NH + h) * HDIM;
    #pragma unroll
    for (int n = 0; n < 8; n++) {
        int col = n * 8 + 2 * qd;
        *reinterpret_cast<float2*>(Ob0 + col) =
            make_float2(o[n][0] * inv0, o[n][1] * inv0);
        *reinterpret_cast<float2*>(Ob1 + col) =
            make_float2(o[n][2] * inv1, o[n][3] * inv1);
    }
}

extern "C" void kernel_launch(void* const* d_in, const int* in_sizes, int n_in,
                              void* d_out, int out_size)
{
    const float* Q = (const float*)d_in[0];
    const float* K = (const float*)d_in[1];
    const float* V = (const float*)d_in[2];
    float* O = (float*)d_out;

    // fused prepass: K relayout + V transpose to fp16 scratch
    conv_kernel<<<dim3(SEQL / 64, BATCH * NH), 256>>>(K, V);

    cudaFuncSetAttribute(fa_fp16_kernel,
                         cudaFuncAttributeMaxDynamicSharedMemorySize, SMEM_BYTES);
    dim3 grid(SEQL / BM, BATCH * NH);   // (32, 32)
    fa_fp16_kernel<<<grid, 128, SMEM_BYTES>>>(Q, O);
}